// round 10
// baseline (speedup 1.0000x reference)
#include <cuda_runtime.h>
#include <cuda_fp16.h>
#include <cstdint>
#include <math.h>

// ---------------- problem constants ----------------
#define TOPK 6
#define NE   64
#define ND   2048
#define NF   1408
#define NFS  2816
#define NTOK 8192
#define NA   (NTOK*TOPK)   // 49152 routed assignments
#define CAP  1536

// ---------------- scratch (device globals) ----------------
__device__ int    g_counts[NE];
__device__ int    g_offsets[NE];
__device__ int    g_cursor[NE];
__device__ int    g_tidx[NA];
__device__ float  g_tw[NA];
__device__ int    g_stok[NA];
__device__ int    g_a2p[NA];
__device__ __half g_u [(size_t)NA * NF];    // up proj then act, fp16
__device__ __half g_eo[(size_t)NA * ND];    // expert output rows, fp16
__device__ __half g_su[(size_t)NTOK * NFS]; // shared up then act, fp16

// ---------------- small kernels ----------------
__global__ void zero_kernel() {
    int i = threadIdx.x;
    if (i < NE) { g_counts[i] = 0; g_cursor[i] = 0; }
}

__global__ void router_kernel(const float* __restrict__ x,
                              const float* __restrict__ gw)
{
    int t = blockIdx.x;
    __shared__ float xs[ND];
    __shared__ float logits[NE];
    const float* xr = x + (size_t)t * ND;
    for (int i = threadIdx.x; i < ND; i += blockDim.x) xs[i] = xr[i];
    __syncthreads();

    int warp = threadIdx.x >> 5, lane = threadIdx.x & 31;
    #pragma unroll
    for (int e8 = 0; e8 < 8; e8++) {
        int e = warp * 8 + e8;
        const float* w = gw + (size_t)e * ND;
        float s = 0.f;
        for (int i = lane; i < ND; i += 32) s += xs[i] * w[i];
        #pragma unroll
        for (int o = 16; o; o >>= 1) s += __shfl_down_sync(0xffffffffu, s, o);
        if (lane == 0) logits[e] = s;
    }
    __syncthreads();

    if (threadIdx.x == 0) {
        int idx6[TOPK]; float val6[TOPK];
        unsigned long long used = 0ull;
        for (int k = 0; k < TOPK; k++) {
            float best = -INFINITY; int bi = 0;
            for (int e = 0; e < NE; e++) {
                if (!((used >> e) & 1ull) && logits[e] > best) { best = logits[e]; bi = e; }
            }
            used |= 1ull << bi; idx6[k] = bi; val6[k] = best;
        }
        float m = val6[0], sum = 0.f, w6[TOPK];
        #pragma unroll
        for (int k = 0; k < TOPK; k++) { w6[k] = expf(val6[k] - m); sum += w6[k]; }
        float inv = 1.f / sum;
        #pragma unroll
        for (int k = 0; k < TOPK; k++) {
            g_tidx[t * TOPK + k] = idx6[k];
            g_tw  [t * TOPK + k] = w6[k] * inv;
            atomicAdd(&g_counts[idx6[k]], 1);
        }
    }
}

__global__ void prefix_kernel() {
    if (threadIdx.x == 0) {
        int acc = 0;
        for (int e = 0; e < NE; e++) { g_offsets[e] = acc; acc += g_counts[e]; }
    }
}

__global__ void scatter_kernel() {
    int a = blockIdx.x * blockDim.x + threadIdx.x;
    if (a >= NA) return;
    int e = g_tidx[a];
    int slot = atomicAdd(&g_cursor[e], 1);
    if (slot < CAP) {
        int p = g_offsets[e] + slot;
        g_stok[p] = a / TOPK;
        g_a2p[a] = p;
    } else {
        g_a2p[a] = -1;
    }
}

// ---------------- fp16 tensor-core GEMM v3 ----------------
// C[m][n] = sum_k A[m][k] * B[n][k]; 256 threads, CTA 256x128, warp 64x64
// (4x2 warp grid), BK=32, 2 smem stages, register-staged prefetch,
// ldmatrix frag loads. Swizzled smem rows of 64B; conflict-free STS/LDSM.

__device__ __forceinline__ uint32_t smem_u32(const void* p) {
    uint32_t a;
    asm("{ .reg .u64 t; cvta.to.shared.u64 t, %1; cvt.u32.u64 %0, t; }" : "=r"(a) : "l"(p));
    return a;
}

// byte offset of (row, h), h = 16B column index (0..3), row-major 64B rows
__device__ __forceinline__ uint32_t swoff(int row, int h) {
    return (uint32_t)(((row >> 1) << 7) +
                      ((((h + ((row & 1) << 2)) ^ ((row >> 1) & 7))) << 4));
}

__device__ __forceinline__ unsigned pack2(float a, float b) {
    __half2 h = __floats2half2_rn(a, b);
    return *(unsigned*)&h;
}

__device__ __forceinline__ void ldsm4(unsigned& r0, unsigned& r1, unsigned& r2,
                                      unsigned& r3, uint32_t addr) {
    asm volatile("ldmatrix.sync.aligned.m8n8.x4.shared.b16 {%0,%1,%2,%3}, [%4];"
                 : "=r"(r0), "=r"(r1), "=r"(r2), "=r"(r3) : "r"(addr));
}

__device__ __forceinline__ void mma_f16(float d[4], const unsigned a[4],
                                        const unsigned b[2], const float c[4]) {
    asm volatile(
        "mma.sync.aligned.m16n8k16.row.col.f32.f16.f16.f32 "
        "{%0,%1,%2,%3},{%4,%5,%6,%7},{%8,%9},{%10,%11,%12,%13};\n"
        : "=f"(d[0]), "=f"(d[1]), "=f"(d[2]), "=f"(d[3])
        : "r"(a[0]), "r"(a[1]), "r"(a[2]), "r"(a[3]),
          "r"(b[0]), "r"(b[1]),
          "f"(c[0]), "f"(c[1]), "f"(c[2]), "f"(c[3]));
}

#define MAT_A_BYTES 16384           // 256 rows x 64B
#define MAT_B_BYTES 8192            // 128 rows x 64B
#define STAGE_BYTES (MAT_A_BYTES + MAT_B_BYTES)   // 24576

template<int AH, int OH, int FUSE>
__global__ __launch_bounds__(256)
void gemm16(const void* __restrict__ Av, int lda,
            const float* __restrict__ B,
            void* __restrict__ Cv, int ldc,
            int M, int Ntot, int K,
            const int* __restrict__ rowmap,
            const int* __restrict__ offsets,
            const int* __restrict__ counts)
{
    __shared__ char sm[2 * STAGE_BYTES];   // 48KB

    int rowbase = 0;
    if (offsets) {
        int e = blockIdx.z;
        rowbase = offsets[e];
        M = min(counts[e], CAP);
        B += (size_t)e * Ntot * K;
    }
    int m0 = blockIdx.y * 256;
    if (m0 >= M) return;
    int n0 = blockIdx.x * 128;

    int tid = threadIdx.x, warp = tid >> 5, lane = tid & 31;
    int wm = warp >> 1, wn = warp & 1;     // 4 x 2 warp grid
    int mb = wm * 64, nb = wn * 64;
    int grp = lane >> 2, tig = lane & 3;

    // ---- fill mapping: r0 = tid>>2 (0..63), q = tid&3 (16B quad) ----
    int r0 = tid >> 2, q = tid & 3;
    int q8 = q * 8;
    int aphys[4];               // A rows r0 + 64i
    uint32_t stA[4];
    const float* bp[2];         // B rows r0 + 64i
    uint32_t stB[2];
    #pragma unroll
    for (int i = 0; i < 4; i++) {
        int row = r0 + 64 * i;
        int ar = min(m0 + row, M - 1);
        aphys[i] = rowmap ? rowmap[rowbase + ar] : (rowbase + ar);
        stA[i] = swoff(row, q);
    }
    #pragma unroll
    for (int i = 0; i < 2; i++) {
        int row = r0 + 64 * i;
        bp[i] = B + (size_t)(n0 + row) * K + q8;
        stB[i] = swoff(row, q);
    }

    // ---- ldmatrix lane mapping ----
    int lrow = (lane & 7) + 8 * ((lane >> 3) & 1);
    int lh = (lane >> 4) & 1;
    uint32_t sbase = smem_u32(sm);
    uint32_t aoff[2] = { swoff(mb + lrow, lh), swoff(mb + lrow, 2 + lh) };
    uint32_t boff[2] = { swoff(nb + lrow, lh), swoff(nb + lrow, 2 + lh) };

    float acc[4][8][4];
    #pragma unroll
    for (int mt = 0; mt < 4; mt++)
        #pragma unroll
        for (int nt = 0; nt < 8; nt++)
            #pragma unroll
            for (int j = 0; j < 4; j++) acc[mt][nt][j] = 0.f;

    // staging registers
    uint4 rah[4];          // AH=1
    float4 raf[4][2];      // AH=0
    float4 rbf[2][2];

    const int nch = K / 32;

    auto load_chunk = [&](int kc) {
        #pragma unroll
        for (int i = 0; i < 4; i++) {
            if (AH) {
                const __half* Ah = ((const __half*)Av) + (size_t)aphys[i] * lda + kc + q8;
                rah[i] = *(const uint4*)Ah;
            } else {
                const float* Af = ((const float*)Av) + (size_t)aphys[i] * lda + kc + q8;
                raf[i][0] = *(const float4*)Af;
                raf[i][1] = *(const float4*)(Af + 4);
            }
        }
        #pragma unroll
        for (int i = 0; i < 2; i++) {
            rbf[i][0] = *(const float4*)(bp[i] + kc);
            rbf[i][1] = *(const float4*)(bp[i] + kc + 4);
        }
    };

    auto sts_chunk = [&](int s) {
        char* sa = sm + s * STAGE_BYTES;
        char* sb = sa + MAT_A_BYTES;
        #pragma unroll
        for (int i = 0; i < 4; i++) {
            if (AH) {
                *(uint4*)(sa + stA[i]) = rah[i];
            } else {
                *(uint4*)(sa + stA[i]) = make_uint4(
                    pack2(raf[i][0].x, raf[i][0].y), pack2(raf[i][0].z, raf[i][0].w),
                    pack2(raf[i][1].x, raf[i][1].y), pack2(raf[i][1].z, raf[i][1].w));
            }
        }
        #pragma unroll
        for (int i = 0; i < 2; i++) {
            *(uint4*)(sb + stB[i]) = make_uint4(
                pack2(rbf[i][0].x, rbf[i][0].y), pack2(rbf[i][0].z, rbf[i][0].w),
                pack2(rbf[i][1].x, rbf[i][1].y), pack2(rbf[i][1].z, rbf[i][1].w));
        }
    };

    // prolog: chunk0 -> stage0; chunk1 in regs
    load_chunk(0);
    sts_chunk(0);
    if (nch > 1) load_chunk(32);
    __syncthreads();

    for (int it = 0; it < nch; it++) {
        int s = it & 1;

        if (it + 1 < nch) {
            sts_chunk(s ^ 1);
            if (it + 2 < nch) load_chunk((it + 2) * 32);
        }

        uint32_t sA = sbase + s * STAGE_BYTES;
        uint32_t sB = sA + MAT_A_BYTES;
        #pragma unroll
        for (int ks = 0; ks < 2; ks++) {
            unsigned af[4][4], bf[8][2];
            #pragma unroll
            for (int mt = 0; mt < 4; mt++)
                ldsm4(af[mt][0], af[mt][1], af[mt][2], af[mt][3],
                      sA + aoff[ks] + mt * 1024);
            #pragma unroll
            for (int np = 0; np < 4; np++) {
                unsigned t0, t1, t2, t3;
                ldsm4(t0, t1, t2, t3, sB + boff[ks] + np * 1024);
                bf[2 * np][0] = t0;     bf[2 * np][1] = t2;
                bf[2 * np + 1][0] = t1; bf[2 * np + 1][1] = t3;
            }
            #pragma unroll
            for (int mt = 0; mt < 4; mt++)
                #pragma unroll
                for (int nt = 0; nt < 8; nt++)
                    mma_f16(acc[mt][nt], af[mt], bf[nt], acc[mt][nt]);
        }
        __syncthreads();
    }

    // ---- epilogue ----
    #pragma unroll
    for (int mt = 0; mt < 4; mt++) {
        int row0 = m0 + mb + mt * 16 + grp;
        #pragma unroll
        for (int nt = 0; nt < 8; nt++) {
            int col = n0 + nb + nt * 8 + tig * 2;
            #pragma unroll
            for (int h = 0; h < 2; h++) {
                int row = row0 + h * 8;
                if (row >= M) continue;
                float v0 = acc[mt][nt][2 * h], v1 = acc[mt][nt][2 * h + 1];
                if (OH) {
                    __half2* p = (__half2*)(((__half*)Cv) + (size_t)(rowbase + row) * ldc + col);
                    if (FUSE) {
                        float2 u = __half22float2(*p);
                        v0 = (v0 / (1.f + __expf(-v0))) * u.x;
                        v1 = (v1 / (1.f + __expf(-v1))) * u.y;
                    }
                    *p = __floats2half2_rn(v0, v1);
                } else {
                    float* p = ((float*)Cv) + (size_t)(rowbase + row) * ldc + col;
                    p[0] = v0; p[1] = v1;
                }
            }
        }
    }
}

// out[t][2d..2d+1] += sum_k w(t,k) * eo_h[pos(t,k)][2d..2d+1]
__global__ void combine_kernel(float* __restrict__ out) {
    int t = blockIdx.y;
    int d2 = blockIdx.x * blockDim.x + threadIdx.x;   // half2 index
    float2 s = *(float2*)&out[(size_t)t * ND + 2 * d2];
    #pragma unroll
    for (int k = 0; k < TOPK; k++) {
        int p = g_a2p[t * TOPK + k];
        if (p >= 0) {
            float w = g_tw[t * TOPK + k];
            __half2 h = *(__half2*)&g_eo[(size_t)p * ND + 2 * d2];
            float2 v = __half22float2(h);
            s.x += w * v.x; s.y += w * v.y;
        }
    }
    *(float2*)&out[(size_t)t * ND + 2 * d2] = s;
}

// ---------------- launch ----------------
extern "C" void kernel_launch(void* const* d_in, const int* in_sizes, int n_in,
                              void* d_out, int out_size)
{
    const float* x       = (const float*)d_in[0];
    const float* gate_w  = (const float*)d_in[1];
    const float* w_gate  = (const float*)d_in[2];
    const float* w_up    = (const float*)d_in[3];
    const float* w_down  = (const float*)d_in[4];
    const float* sh_gate = (const float*)d_in[5];
    const float* sh_up   = (const float*)d_in[6];
    const float* sh_down = (const float*)d_in[7];
    float* out = (float*)d_out;

    void *pu, *peo, *psu, *pstok, *poff, *pcnt;
    cudaGetSymbolAddress(&pu,   g_u);
    cudaGetSymbolAddress(&peo,  g_eo);
    cudaGetSymbolAddress(&psu,  g_su);
    cudaGetSymbolAddress(&pstok, g_stok);
    cudaGetSymbolAddress(&poff, g_offsets);
    cudaGetSymbolAddress(&pcnt, g_counts);
    __half* ubuf = (__half*)pu;  __half* eo = (__half*)peo;  __half* su = (__half*)psu;
    int* stok = (int*)pstok;     int* offs = (int*)poff;     int* cnts = (int*)pcnt;

    // 1) router + dispatch
    zero_kernel<<<1, 64>>>();
    router_kernel<<<NTOK, 256>>>(x, gate_w);
    prefix_kernel<<<1, 1>>>();
    scatter_kernel<<<(NA + 255) / 256, 256>>>();

    // 2) routed experts: up -> ubuf(fp16); gate fused silu*u -> ubuf; down -> eo(fp16)
    {
        dim3 grid(NF / 128, CAP / 256, NE);
        gemm16<0,1,0><<<grid, 256>>>(x, ND, w_up,   ubuf, NF, 0, NF, ND, stok, offs, cnts);
        gemm16<0,1,1><<<grid, 256>>>(x, ND, w_gate, ubuf, NF, 0, NF, ND, stok, offs, cnts);
    }
    {
        dim3 grid(ND / 128, CAP / 256, NE);
        gemm16<1,1,0><<<grid, 256>>>(ubuf, NF, w_down, eo, ND, 0, ND, NF, nullptr, offs, cnts);
    }

    // 3) shared expert: up -> su(fp16); gate fused -> su; down -> out(fp32)
    {
        dim3 grid(NFS / 128, NTOK / 256, 1);
        gemm16<0,1,0><<<grid, 256>>>(x, ND, sh_up,   su, NFS, NTOK, NFS, ND, nullptr, nullptr, nullptr);
        gemm16<0,1,1><<<grid, 256>>>(x, ND, sh_gate, su, NFS, NTOK, NFS, ND, nullptr, nullptr, nullptr);
    }
    {
        dim3 grid(ND / 128, NTOK / 256, 1);
        gemm16<1,0,0><<<grid, 256>>>(su, NFS, sh_down, out, ND, NTOK, ND, NFS, nullptr, nullptr, nullptr);
    }

    // 4) combine routed outputs into d_out
    {
        dim3 grid((ND / 2) / 256, NTOK);
        combine_kernel<<<grid, 256>>>(out);
    }
}

// round 11
// speedup vs baseline: 1.1190x; 1.1190x over previous
#include <cuda_runtime.h>
#include <cuda_fp16.h>
#include <cstdint>
#include <math.h>

// ---------------- problem constants ----------------
#define TOPK 6
#define NE   64
#define ND   2048
#define NF   1408
#define NFS  2816
#define NTOK 8192
#define NA   (NTOK*TOPK)   // 49152 routed assignments
#define CAP  1536

// ---------------- scratch (device globals) ----------------
__device__ int    g_counts[NE];
__device__ int    g_offsets[NE];
__device__ int    g_cursor[NE];
__device__ int    g_tidx[NA];
__device__ float  g_tw[NA];
__device__ int    g_stok[NA];
__device__ int    g_a2p[NA];
__device__ __half g_xh[(size_t)NTOK * ND];  // x pre-converted to fp16
__device__ __half g_u [(size_t)NA * NF];    // up proj then act, fp16
__device__ __half g_eo[(size_t)NA * ND];    // expert output rows, fp16
__device__ __half g_su[(size_t)NTOK * NFS]; // shared up then act, fp16

// ---------------- small kernels ----------------
__global__ void zero_kernel() {
    int i = threadIdx.x;
    if (i < NE) { g_counts[i] = 0; g_cursor[i] = 0; }
}

// convert x (fp32) -> g_xh (fp16), 4 elems/thread
__global__ void cvt_x_kernel(const float* __restrict__ x) {
    size_t i = ((size_t)blockIdx.x * blockDim.x + threadIdx.x) * 4;
    float4 v = *(const float4*)(x + i);
    __half2 h0 = __floats2half2_rn(v.x, v.y);
    __half2 h1 = __floats2half2_rn(v.z, v.w);
    *(uint2*)&g_xh[i] = make_uint2(*(unsigned*)&h0, *(unsigned*)&h1);
}

__global__ void router_kernel(const float* __restrict__ x,
                              const float* __restrict__ gw)
{
    int t = blockIdx.x;
    __shared__ float xs[ND];
    __shared__ float logits[NE];
    const float* xr = x + (size_t)t * ND;
    for (int i = threadIdx.x; i < ND; i += blockDim.x) xs[i] = xr[i];
    __syncthreads();

    int warp = threadIdx.x >> 5, lane = threadIdx.x & 31;
    #pragma unroll
    for (int e8 = 0; e8 < 8; e8++) {
        int e = warp * 8 + e8;
        const float* w = gw + (size_t)e * ND;
        float s = 0.f;
        for (int i = lane; i < ND; i += 32) s += xs[i] * w[i];
        #pragma unroll
        for (int o = 16; o; o >>= 1) s += __shfl_down_sync(0xffffffffu, s, o);
        if (lane == 0) logits[e] = s;
    }
    __syncthreads();

    if (threadIdx.x == 0) {
        int idx6[TOPK]; float val6[TOPK];
        unsigned long long used = 0ull;
        for (int k = 0; k < TOPK; k++) {
            float best = -INFINITY; int bi = 0;
            for (int e = 0; e < NE; e++) {
                if (!((used >> e) & 1ull) && logits[e] > best) { best = logits[e]; bi = e; }
            }
            used |= 1ull << bi; idx6[k] = bi; val6[k] = best;
        }
        float m = val6[0], sum = 0.f, w6[TOPK];
        #pragma unroll
        for (int k = 0; k < TOPK; k++) { w6[k] = expf(val6[k] - m); sum += w6[k]; }
        float inv = 1.f / sum;
        #pragma unroll
        for (int k = 0; k < TOPK; k++) {
            g_tidx[t * TOPK + k] = idx6[k];
            g_tw  [t * TOPK + k] = w6[k] * inv;
            atomicAdd(&g_counts[idx6[k]], 1);
        }
    }
}

__global__ void prefix_kernel() {
    if (threadIdx.x == 0) {
        int acc = 0;
        for (int e = 0; e < NE; e++) { g_offsets[e] = acc; acc += g_counts[e]; }
    }
}

__global__ void scatter_kernel() {
    int a = blockIdx.x * blockDim.x + threadIdx.x;
    if (a >= NA) return;
    int e = g_tidx[a];
    int slot = atomicAdd(&g_cursor[e], 1);
    if (slot < CAP) {
        int p = g_offsets[e] + slot;
        g_stok[p] = a / TOPK;
        g_a2p[a] = p;
    } else {
        g_a2p[a] = -1;
    }
}

// ---------------- fp16 tensor-core GEMM (R8 config) ----------------
// C[m][n] = sum_k A[m][k] * B[n][k]; 128 threads, CTA 128x128, warp 64x64,
// BK=32, 2 smem stages, register-staged prefetch, ldmatrix frag loads.

__device__ __forceinline__ uint32_t smem_u32(const void* p) {
    uint32_t a;
    asm("{ .reg .u64 t; cvta.to.shared.u64 t, %1; cvt.u32.u64 %0, t; }" : "=r"(a) : "l"(p));
    return a;
}

// byte offset of (row, h), h = 16B column index (0..3), swizzled 64B rows
__device__ __forceinline__ uint32_t swoff(int row, int h) {
    return (uint32_t)(((row >> 1) << 7) +
                      ((((h + ((row & 1) << 2)) ^ ((row >> 1) & 7))) << 4));
}

__device__ __forceinline__ unsigned pack2(float a, float b) {
    __half2 h = __floats2half2_rn(a, b);
    return *(unsigned*)&h;
}

__device__ __forceinline__ void ldsm4(unsigned& r0, unsigned& r1, unsigned& r2,
                                      unsigned& r3, uint32_t addr) {
    asm volatile("ldmatrix.sync.aligned.m8n8.x4.shared.b16 {%0,%1,%2,%3}, [%4];"
                 : "=r"(r0), "=r"(r1), "=r"(r2), "=r"(r3) : "r"(addr));
}

__device__ __forceinline__ void mma_f16(float d[4], const unsigned a[4],
                                        const unsigned b[2], const float c[4]) {
    asm volatile(
        "mma.sync.aligned.m16n8k16.row.col.f32.f16.f16.f32 "
        "{%0,%1,%2,%3},{%4,%5,%6,%7},{%8,%9},{%10,%11,%12,%13};\n"
        : "=f"(d[0]), "=f"(d[1]), "=f"(d[2]), "=f"(d[3])
        : "r"(a[0]), "r"(a[1]), "r"(a[2]), "r"(a[3]),
          "r"(b[0]), "r"(b[1]),
          "f"(c[0]), "f"(c[1]), "f"(c[2]), "f"(c[3]));
}

#define MAT_BYTES   8192            // 128 rows x 64B
#define STAGE_BYTES 16384           // A + B

template<int AH, int OH, int FUSE>
__global__ __launch_bounds__(128)
void gemm16(const void* __restrict__ Av, int lda,
            const float* __restrict__ B,
            void* __restrict__ Cv, int ldc,
            int M, int Ntot, int K,
            const int* __restrict__ rowmap,
            const int* __restrict__ offsets,
            const int* __restrict__ counts)
{
    __shared__ char sm[2 * STAGE_BYTES];

    int rowbase = 0;
    if (offsets) {
        int e = blockIdx.z;
        rowbase = offsets[e];
        M = min(counts[e], CAP);
        B += (size_t)e * Ntot * K;
    }
    int m0 = blockIdx.y * 128;
    if (m0 >= M) return;
    int n0 = blockIdx.x * 128;

    int tid = threadIdx.x, warp = tid >> 5, lane = tid & 31;
    int wm = warp >> 1, wn = warp & 1;
    int mb = wm * 64, nb = wn * 64;
    int grp = lane >> 2, tig = lane & 3;

    // ---- fill mapping: thread (r0 = tid>>2, q = tid&3) covers rows r0+32i ----
    int r0 = tid >> 2, q = tid & 3;
    int q8 = q * 8;
    int aphys[4];
    const float* bp[4];
    uint32_t stoff[4];
    #pragma unroll
    for (int i = 0; i < 4; i++) {
        int row = r0 + 32 * i;
        int ar = min(m0 + row, M - 1);
        aphys[i] = rowmap ? rowmap[rowbase + ar] : (rowbase + ar);
        bp[i] = B + (size_t)(n0 + row) * K + q8;
        stoff[i] = swoff(row, q);
    }

    // ---- ldmatrix lane mapping ----
    int lrow = (lane & 7) + 8 * ((lane >> 3) & 1);
    int lh = (lane >> 4) & 1;
    uint32_t sbase = smem_u32(sm);
    uint32_t aoff[2] = { swoff(mb + lrow, lh), swoff(mb + lrow, 2 + lh) };
    uint32_t boff[2] = { swoff(nb + lrow, lh), swoff(nb + lrow, 2 + lh) };

    float acc[4][8][4];
    #pragma unroll
    for (int mt = 0; mt < 4; mt++)
        #pragma unroll
        for (int nt = 0; nt < 8; nt++)
            #pragma unroll
            for (int j = 0; j < 4; j++) acc[mt][nt][j] = 0.f;

    // staging registers
    uint4 rah[4];          // AH=1
    float4 raf[4][2];      // AH=0
    float4 rbf[4][2];

    const int nch = K / 32;

    auto load_chunk = [&](int kc) {
        #pragma unroll
        for (int i = 0; i < 4; i++) {
            if (AH) {
                const __half* Ah = ((const __half*)Av) + (size_t)aphys[i] * lda + kc + q8;
                rah[i] = *(const uint4*)Ah;
            } else {
                const float* Af = ((const float*)Av) + (size_t)aphys[i] * lda + kc + q8;
                raf[i][0] = *(const float4*)Af;
                raf[i][1] = *(const float4*)(Af + 4);
            }
            rbf[i][0] = *(const float4*)(bp[i] + kc);
            rbf[i][1] = *(const float4*)(bp[i] + kc + 4);
        }
    };

    auto sts_chunk = [&](int s) {
        char* sa = sm + s * STAGE_BYTES;
        char* sb = sa + MAT_BYTES;
        #pragma unroll
        for (int i = 0; i < 4; i++) {
            if (AH) {
                *(uint4*)(sa + stoff[i]) = rah[i];
            } else {
                *(uint4*)(sa + stoff[i]) = make_uint4(
                    pack2(raf[i][0].x, raf[i][0].y), pack2(raf[i][0].z, raf[i][0].w),
                    pack2(raf[i][1].x, raf[i][1].y), pack2(raf[i][1].z, raf[i][1].w));
            }
            *(uint4*)(sb + stoff[i]) = make_uint4(
                pack2(rbf[i][0].x, rbf[i][0].y), pack2(rbf[i][0].z, rbf[i][0].w),
                pack2(rbf[i][1].x, rbf[i][1].y), pack2(rbf[i][1].z, rbf[i][1].w));
        }
    };

    // prolog: chunk0 -> stage0; chunk1 in regs
    load_chunk(0);
    sts_chunk(0);
    if (nch > 1) load_chunk(32);
    __syncthreads();

    for (int it = 0; it < nch; it++) {
        int s = it & 1;

        if (it + 1 < nch) {
            sts_chunk(s ^ 1);
            if (it + 2 < nch) load_chunk((it + 2) * 32);
        }

        uint32_t sA = sbase + s * STAGE_BYTES;
        uint32_t sB = sA + MAT_BYTES;
        #pragma unroll
        for (int ks = 0; ks < 2; ks++) {
            unsigned af[4][4], bf[8][2];
            #pragma unroll
            for (int mt = 0; mt < 4; mt++)
                ldsm4(af[mt][0], af[mt][1], af[mt][2], af[mt][3],
                      sA + aoff[ks] + mt * 1024);
            #pragma unroll
            for (int np = 0; np < 4; np++) {
                unsigned t0, t1, t2, t3;
                ldsm4(t0, t1, t2, t3, sB + boff[ks] + np * 1024);
                bf[2 * np][0] = t0;     bf[2 * np][1] = t2;
                bf[2 * np + 1][0] = t1; bf[2 * np + 1][1] = t3;
            }
            #pragma unroll
            for (int mt = 0; mt < 4; mt++)
                #pragma unroll
                for (int nt = 0; nt < 8; nt++)
                    mma_f16(acc[mt][nt], af[mt], bf[nt], acc[mt][nt]);
        }
        __syncthreads();
    }

    // ---- epilogue ----
    #pragma unroll
    for (int mt = 0; mt < 4; mt++) {
        int row0 = m0 + mb + mt * 16 + grp;
        #pragma unroll
        for (int nt = 0; nt < 8; nt++) {
            int col = n0 + nb + nt * 8 + tig * 2;
            #pragma unroll
            for (int h = 0; h < 2; h++) {
                int row = row0 + h * 8;
                if (row >= M) continue;
                float v0 = acc[mt][nt][2 * h], v1 = acc[mt][nt][2 * h + 1];
                if (OH) {
                    __half2* p = (__half2*)(((__half*)Cv) + (size_t)(rowbase + row) * ldc + col);
                    if (FUSE) {
                        float2 u = __half22float2(*p);
                        v0 = (v0 / (1.f + __expf(-v0))) * u.x;
                        v1 = (v1 / (1.f + __expf(-v1))) * u.y;
                    }
                    *p = __floats2half2_rn(v0, v1);
                } else {
                    float* p = ((float*)Cv) + (size_t)(rowbase + row) * ldc + col;
                    p[0] = v0; p[1] = v1;
                }
            }
        }
    }
}

// out[t][2d..2d+1] += sum_k w(t,k) * eo_h[pos(t,k)][2d..2d+1]
__global__ void combine_kernel(float* __restrict__ out) {
    int t = blockIdx.y;
    int d2 = blockIdx.x * blockDim.x + threadIdx.x;   // half2 index
    float2 s = *(float2*)&out[(size_t)t * ND + 2 * d2];
    #pragma unroll
    for (int k = 0; k < TOPK; k++) {
        int p = g_a2p[t * TOPK + k];
        if (p >= 0) {
            float w = g_tw[t * TOPK + k];
            __half2 h = *(__half2*)&g_eo[(size_t)p * ND + 2 * d2];
            float2 v = __half22float2(h);
            s.x += w * v.x; s.y += w * v.y;
        }
    }
    *(float2*)&out[(size_t)t * ND + 2 * d2] = s;
}

// ---------------- launch ----------------
extern "C" void kernel_launch(void* const* d_in, const int* in_sizes, int n_in,
                              void* d_out, int out_size)
{
    const float* x       = (const float*)d_in[0];
    const float* gate_w  = (const float*)d_in[1];
    const float* w_gate  = (const float*)d_in[2];
    const float* w_up    = (const float*)d_in[3];
    const float* w_down  = (const float*)d_in[4];
    const float* sh_gate = (const float*)d_in[5];
    const float* sh_up   = (const float*)d_in[6];
    const float* sh_down = (const float*)d_in[7];
    float* out = (float*)d_out;

    void *pxh, *pu, *peo, *psu, *pstok, *poff, *pcnt;
    cudaGetSymbolAddress(&pxh,  g_xh);
    cudaGetSymbolAddress(&pu,   g_u);
    cudaGetSymbolAddress(&peo,  g_eo);
    cudaGetSymbolAddress(&psu,  g_su);
    cudaGetSymbolAddress(&pstok, g_stok);
    cudaGetSymbolAddress(&poff, g_offsets);
    cudaGetSymbolAddress(&pcnt, g_counts);
    __half* xh = (__half*)pxh;
    __half* ubuf = (__half*)pu;  __half* eo = (__half*)peo;  __half* su = (__half*)psu;
    int* stok = (int*)pstok;     int* offs = (int*)poff;     int* cnts = (int*)pcnt;

    // 1) router + dispatch (+ x conversion, overlappable)
    zero_kernel<<<1, 64>>>();
    cvt_x_kernel<<<(NTOK * ND / 4 + 255) / 256, 256>>>(x);
    router_kernel<<<NTOK, 256>>>(x, gate_w);
    prefix_kernel<<<1, 1>>>();
    scatter_kernel<<<(NA + 255) / 256, 256>>>();

    // 2) routed experts: up -> ubuf(fp16); gate fused silu*u -> ubuf; down -> eo(fp16)
    {
        dim3 grid(NF / 128, CAP / 128, NE);
        gemm16<1,1,0><<<grid, 128>>>(xh, ND, w_up,   ubuf, NF, 0, NF, ND, stok, offs, cnts);
        gemm16<1,1,1><<<grid, 128>>>(xh, ND, w_gate, ubuf, NF, 0, NF, ND, stok, offs, cnts);
    }
    {
        dim3 grid(ND / 128, CAP / 128, NE);
        gemm16<1,1,0><<<grid, 128>>>(ubuf, NF, w_down, eo, ND, 0, ND, NF, nullptr, offs, cnts);
    }

    // 3) shared expert: up -> su(fp16); gate fused -> su; down -> out(fp32)
    {
        dim3 grid(NFS / 128, NTOK / 128, 1);
        gemm16<1,1,0><<<grid, 128>>>(xh, ND, sh_up,   su, NFS, NTOK, NFS, ND, nullptr, nullptr, nullptr);
        gemm16<1,1,1><<<grid, 128>>>(xh, ND, sh_gate, su, NFS, NTOK, NFS, ND, nullptr, nullptr, nullptr);
    }
    {
        dim3 grid(ND / 128, NTOK / 128, 1);
        gemm16<1,0,0><<<grid, 128>>>(su, NFS, sh_down, out, ND, NTOK, ND, NFS, nullptr, nullptr, nullptr);
    }

    // 4) combine routed outputs into d_out
    {
        dim3 grid((ND / 2) / 256, NTOK);
        combine_kernel<<<grid, 256>>>(out);
    }
}